// round 1
// baseline (speedup 1.0000x reference)
#include <cuda_runtime.h>

// Problem constants (fixed shapes per reference)
#define NTOK   16384      // B*S
#define DIN    2048
#define DOUT   2048
#define RANK   16
#define NADAPT 8

// Scratch for u[n, r] = scaling[aid] * (x[n] @ A[aid]^T)  (zero when aid==0)
__device__ float g_u[NTOK * RANK];

// ---------------------------------------------------------------------------
// Kernel A: one warp per token computes the rank-16 projection u.
// ---------------------------------------------------------------------------
__global__ void __launch_bounds__(256) lora_u_kernel(
    const float* __restrict__ x,
    const int*   __restrict__ mapping,
    const float* __restrict__ lora_a,
    const float* __restrict__ scaling)
{
    int warp = (blockIdx.x * blockDim.x + threadIdx.x) >> 5;
    int lane = threadIdx.x & 31;
    if (warp >= NTOK) return;

    int aid = mapping[warp];
    if (aid == 0) {
        if (lane < RANK) g_u[warp * RANK + lane] = 0.0f;
        return;
    }

    const float* xa = x + (size_t)warp * DIN;
    const float* A  = lora_a + (size_t)(aid - 1) * RANK * DIN;

    float acc[RANK];
#pragma unroll
    for (int r = 0; r < RANK; r++) acc[r] = 0.0f;

    // 2048 / (32 lanes * 4) = 16 iterations, float4 vectorized
    for (int d0 = lane * 4; d0 < DIN; d0 += 32 * 4) {
        float4 xv = *(const float4*)(xa + d0);
#pragma unroll
        for (int r = 0; r < RANK; r++) {
            float4 av = *(const float4*)(A + r * DIN + d0);
            acc[r] += xv.x * av.x + xv.y * av.y + xv.z * av.z + xv.w * av.w;
        }
    }

    float s = scaling[aid - 1];
#pragma unroll
    for (int r = 0; r < RANK; r++) {
        float v = acc[r];
#pragma unroll
        for (int off = 16; off; off >>= 1)
            v += __shfl_xor_sync(0xffffffffu, v, off);
        if (lane == r) g_u[warp * RANK + r] = v * s;
    }
}

// ---------------------------------------------------------------------------
// Kernel B: 128x128x8 fp32 SGEMM (8x8 per thread, 256 threads) with fused
// bias + LoRA-B epilogue:  out[n,o] = x[n,:]@W[o,:] + bias[o] + u[n,:]@B[aid,o,:]
// ---------------------------------------------------------------------------
#define BN 128
#define BO 128
#define BK 8

__global__ void __launch_bounds__(256) fused_gemm_kernel(
    const float* __restrict__ x,
    const int*   __restrict__ mapping,
    const float* __restrict__ W,
    const float* __restrict__ bias,
    const float* __restrict__ lora_b,
    float*       __restrict__ out)
{
    __shared__ float As[BK][BN];
    __shared__ float Bs[BK][BO];

    const int tid   = threadIdx.x;
    const int nBase = blockIdx.y * BN;
    const int oBase = blockIdx.x * BO;
    const int tx = tid & 15;        // 16 thread-cols
    const int ty = tid >> 4;        // 16 thread-rows

    // global staging: each thread loads one float4 of A-tile and one of B-tile
    const int lrow = tid >> 1;          // 0..127
    const int lk4  = (tid & 1) * 4;     // 0 or 4

    const float* xg = x + (size_t)(nBase + lrow) * DIN + lk4;
    const float* wg = W + (size_t)(oBase + lrow) * DIN + lk4;

    float acc[8][8];
#pragma unroll
    for (int i = 0; i < 8; i++)
#pragma unroll
        for (int j = 0; j < 8; j++) acc[i][j] = 0.0f;

    for (int k0 = 0; k0 < DIN; k0 += BK) {
        float4 xv = *(const float4*)(xg + k0);
        float4 wv = *(const float4*)(wg + k0);
        As[lk4 + 0][lrow] = xv.x;  As[lk4 + 1][lrow] = xv.y;
        As[lk4 + 2][lrow] = xv.z;  As[lk4 + 3][lrow] = xv.w;
        Bs[lk4 + 0][lrow] = wv.x;  Bs[lk4 + 1][lrow] = wv.y;
        Bs[lk4 + 2][lrow] = wv.z;  Bs[lk4 + 3][lrow] = wv.w;
        __syncthreads();

#pragma unroll
        for (int kk = 0; kk < BK; kk++) {
            float a[8], b[8];
            *(float4*)&a[0] = *(const float4*)&As[kk][ty * 8 + 0];
            *(float4*)&a[4] = *(const float4*)&As[kk][ty * 8 + 4];
            *(float4*)&b[0] = *(const float4*)&Bs[kk][tx * 8 + 0];
            *(float4*)&b[4] = *(const float4*)&Bs[kk][tx * 8 + 4];
#pragma unroll
            for (int i = 0; i < 8; i++)
#pragma unroll
                for (int j = 0; j < 8; j++)
                    acc[i][j] += a[i] * b[j];
        }
        __syncthreads();
    }

    // ---- epilogue: bias + LoRA-B + store ----
    const int nRow = nBase + ty * 8;
    const int oCol = oBase + tx * 8;

    float bv[8];
    *(float4*)&bv[0] = *(const float4*)(bias + oCol + 0);
    *(float4*)&bv[4] = *(const float4*)(bias + oCol + 4);

#pragma unroll
    for (int i = 0; i < 8; i++) {
        const int n = nRow + i;
        const int aid = mapping[n];
        if (aid > 0) {
            float ur[RANK];
            const float* up = g_u + (size_t)n * RANK;
            *(float4*)&ur[0]  = *(const float4*)(up + 0);
            *(float4*)&ur[4]  = *(const float4*)(up + 4);
            *(float4*)&ur[8]  = *(const float4*)(up + 8);
            *(float4*)&ur[12] = *(const float4*)(up + 12);
            const float* lbbase = lora_b + ((size_t)(aid - 1) * DOUT + oCol) * RANK;
#pragma unroll
            for (int j = 0; j < 8; j++) {
                const float4* lbp = (const float4*)(lbbase + (size_t)j * RANK);
                float s = 0.0f;
#pragma unroll
                for (int q = 0; q < 4; q++) {
                    float4 lv = lbp[q];
                    s += ur[4*q + 0] * lv.x + ur[4*q + 1] * lv.y
                       + ur[4*q + 2] * lv.z + ur[4*q + 3] * lv.w;
                }
                acc[i][j] += s;
            }
        }
        float4 o0, o1;
        o0.x = acc[i][0] + bv[0];  o0.y = acc[i][1] + bv[1];
        o0.z = acc[i][2] + bv[2];  o0.w = acc[i][3] + bv[3];
        o1.x = acc[i][4] + bv[4];  o1.y = acc[i][5] + bv[5];
        o1.z = acc[i][6] + bv[6];  o1.w = acc[i][7] + bv[7];
        float* op = out + (size_t)n * DOUT + oCol;
        *(float4*)(op + 0) = o0;
        *(float4*)(op + 4) = o1;
    }
}

// ---------------------------------------------------------------------------
// Inputs (metadata order): x, lora_mapping, weight, bias, lora_a, lora_b, scaling
// ---------------------------------------------------------------------------
extern "C" void kernel_launch(void* const* d_in, const int* in_sizes, int n_in,
                              void* d_out, int out_size)
{
    const float* x       = (const float*)d_in[0];
    const int*   mapping = (const int*)  d_in[1];
    const float* weight  = (const float*)d_in[2];
    const float* bias    = (const float*)d_in[3];
    const float* lora_a  = (const float*)d_in[4];
    const float* lora_b  = (const float*)d_in[5];
    const float* scaling = (const float*)d_in[6];
    float*       out     = (float*)d_out;

    // Kernel A: u = scaling * (x @ A^T), one warp per token (8 warps/block)
    lora_u_kernel<<<NTOK / 8, 256>>>(x, mapping, lora_a, scaling);

    // Kernel B: fused GEMM + bias + LoRA-B
    dim3 grid(DOUT / BO, NTOK / BN);
    fused_gemm_kernel<<<grid, 256>>>(x, mapping, weight, bias, lora_b, out);
}

// round 3
// speedup vs baseline: 4.0544x; 4.0544x over previous
#include <cuda_runtime.h>
#include <cstdint>

// ---------------------------------------------------------------------------
// Problem constants
// ---------------------------------------------------------------------------
#define NTOK   16384      // B*S
#define DIN    2048
#define DOUT   2048
#define RANK   16
#define NADAPT 8
#define KEXT   (NADAPT*RANK)    // 128 extra K columns holding LoRA
#define KTOT   (DIN + KEXT)     // 2176

// GEMM tiling
#define BM 128
#define BN 128
#define BK 32
#define NCH (KTOT / BK)         // 68 K-chunks
#define STAGES 3
#define LDP (BK + 4)            // padded smem row: 36 floats (16B-aligned stride)
#define TILE_F (BM * LDP)       // 4608 floats per A/B tile per stage
#define SMEM_BYTES (STAGES * TILE_F * 2 * sizeof(float))   // 110592

// tf32-rounded, K-extended operand buffers
__device__ float g_xr[(size_t)NTOK * KTOT];   // [NTOK, 2176]
__device__ float g_wr[(size_t)DOUT * KTOT];   // [DOUT, 2176]

// ---------------------------------------------------------------------------
// Helpers
// ---------------------------------------------------------------------------
__device__ __forceinline__ float rna_tf32(float f) {
    float r;
    asm("cvt.rna.tf32.f32 %0, %1;" : "=f"(r) : "f"(f));
    return r;
}

__device__ __forceinline__ uint32_t smem_u32(const void* p) {
    uint32_t a;
    asm("{ .reg .u64 t; cvta.to.shared.u64 t, %1; cvt.u32.u64 %0, t; }"
        : "=r"(a) : "l"(p));
    return a;
}

__device__ __forceinline__ void cp_async16(uint32_t dst, const void* src) {
    asm volatile("cp.async.cg.shared.global [%0], [%1], 16;"
                 :: "r"(dst), "l"(src) : "memory");
}

__device__ __forceinline__ void mma_tf32_16888(
    float* c, const uint32_t* a, const uint32_t* b)
{
    asm volatile(
        "mma.sync.aligned.m16n8k8.row.col.f32.tf32.tf32.f32 "
        "{%0,%1,%2,%3}, {%4,%5,%6,%7}, {%8,%9}, {%0,%1,%2,%3};"
        : "+f"(c[0]), "+f"(c[1]), "+f"(c[2]), "+f"(c[3])
        : "r"(a[0]), "r"(a[1]), "r"(a[2]), "r"(a[3]),
          "r"(b[0]), "r"(b[1]));
}

// ---------------------------------------------------------------------------
// Pre-pass X: round x to tf32 into g_xr[:, 0:2048]; compute u = scaling *
// (x @ A[aid]^T) and expand into g_xr[:, 2048 + (aid-1)*16 + r] (zeros else).
// One warp per token.
// ---------------------------------------------------------------------------
__global__ void __launch_bounds__(256) prep_x_kernel(
    const float* __restrict__ x,
    const int*   __restrict__ mapping,
    const float* __restrict__ lora_a,
    const float* __restrict__ scaling)
{
    int warp = (blockIdx.x * blockDim.x + threadIdx.x) >> 5;
    int lane = threadIdx.x & 31;
    if (warp >= NTOK) return;

    const float* xr = x + (size_t)warp * DIN;
    float* orow = g_xr + (size_t)warp * KTOT;
    int aid = mapping[warp];
    const float* A = lora_a + (size_t)(aid > 0 ? aid - 1 : 0) * RANK * DIN;

    float acc[RANK];
#pragma unroll
    for (int r = 0; r < RANK; r++) acc[r] = 0.0f;

    for (int d0 = lane * 4; d0 < DIN; d0 += 128) {
        float4 xv = *(const float4*)(xr + d0);
        float4 ov;
        ov.x = rna_tf32(xv.x); ov.y = rna_tf32(xv.y);
        ov.z = rna_tf32(xv.z); ov.w = rna_tf32(xv.w);
        *(float4*)(orow + d0) = ov;
        if (aid > 0) {
#pragma unroll
            for (int r = 0; r < RANK; r++) {
                float4 av = *(const float4*)(A + r * DIN + d0);
                acc[r] += xv.x * av.x + xv.y * av.y + xv.z * av.z + xv.w * av.w;
            }
        }
    }

    float s = (aid > 0) ? scaling[aid - 1] : 0.0f;
#pragma unroll
    for (int r = 0; r < RANK; r++) {
        float v = acc[r];
#pragma unroll
        for (int off = 16; off; off >>= 1)
            v += __shfl_xor_sync(0xffffffffu, v, off);
        acc[r] = v * s;  // all lanes hold u[r]
    }

    int q = lane & 3;
#pragma unroll
    for (int e4 = 0; e4 < 4; e4++) {
        float uv = (q == 0) ? acc[e4] : (q == 1) ? acc[4 + e4]
                 : (q == 2) ? acc[8 + e4] : acc[12 + e4];
        int e = lane * 4 + e4;             // 0..127
        float v = (aid > 0 && (e >> 4) == (aid - 1)) ? rna_tf32(uv) : 0.0f;
        orow[DIN + e] = v;
    }
}

// ---------------------------------------------------------------------------
// Pre-pass W: round W to tf32 into g_wr[:, 0:2048]; pack rounded lora_b into
// g_wr[o, 2048 + a*16 + r]. One warp per output row.
// ---------------------------------------------------------------------------
__global__ void __launch_bounds__(256) prep_w_kernel(
    const float* __restrict__ W,
    const float* __restrict__ lora_b)
{
    int o = (blockIdx.x * blockDim.x + threadIdx.x) >> 5;
    int lane = threadIdx.x & 31;
    if (o >= DOUT) return;

    const float* wr = W + (size_t)o * DIN;
    float* orow = g_wr + (size_t)o * KTOT;

    for (int d0 = lane * 4; d0 < DIN; d0 += 128) {
        float4 wv = *(const float4*)(wr + d0);
        float4 ov;
        ov.x = rna_tf32(wv.x); ov.y = rna_tf32(wv.y);
        ov.z = rna_tf32(wv.z); ov.w = rna_tf32(wv.w);
        *(float4*)(orow + d0) = ov;
    }

    int e0 = lane * 4;
    int a = e0 >> 4;
    int r0 = e0 & 15;
    float4 lb = *(const float4*)(lora_b + ((size_t)a * DOUT + o) * RANK + r0);
    float4 ov;
    ov.x = rna_tf32(lb.x); ov.y = rna_tf32(lb.y);
    ov.z = rna_tf32(lb.z); ov.w = rna_tf32(lb.w);
    *(float4*)(orow + DIN + e0) = ov;
}

// ---------------------------------------------------------------------------
// mma.sync tf32 GEMM: out[n,o] = g_xr[n,:] . g_wr[o,:] + bias[o]
// CTA tile 128x128x32, 8 warps (2x4), each warp 64x32 via m16n8k8 tiles.
// 3-stage cp.async pipeline, padded smem (conflict-free fragment LDS).
// ---------------------------------------------------------------------------
__global__ void __launch_bounds__(256, 1) gemm_mma_kernel(
    const float* __restrict__ bias, float* __restrict__ out)
{
    extern __shared__ float smem[];
    const int tid  = threadIdx.x;
    const int wid  = tid >> 5;
    const int lane = tid & 31;
    const int gid  = lane >> 2;     // 0..7
    const int tig  = lane & 3;      // 0..3
    const int warpM = wid >> 2;     // 0..1  -> 64 rows
    const int warpN = wid & 3;      // 0..3  -> 32 cols
    const int mBase = blockIdx.y * BM;
    const int oBase = blockIdx.x * BN;

    float* As = smem;                       // [STAGES][BM][LDP]
    float* Bs = smem + STAGES * TILE_F;     // [STAGES][BN][LDP]

    float acc[4][4][4];
#pragma unroll
    for (int mi = 0; mi < 4; mi++)
#pragma unroll
        for (int ni = 0; ni < 4; ni++)
#pragma unroll
            for (int q = 0; q < 4; q++) acc[mi][ni][q] = 0.0f;

    // staging: 4 float4 per thread per tile (128 rows x 8 segs = 1024 = 256*4)
    const int lrow = tid >> 3;          // advances by 32 per t
    const int lseg = tid & 7;

    auto load_stage = [&](int chunk, int slot) {
        float* a = As + slot * TILE_F;
        float* b = Bs + slot * TILE_F;
        const size_t koff = (size_t)chunk * BK + lseg * 4;
#pragma unroll
        for (int t = 0; t < 4; t++) {
            int row = lrow + t * 32;
            cp_async16(smem_u32(a + row * LDP + lseg * 4),
                       g_xr + (size_t)(mBase + row) * KTOT + koff);
            cp_async16(smem_u32(b + row * LDP + lseg * 4),
                       g_wr + (size_t)(oBase + row) * KTOT + koff);
        }
        asm volatile("cp.async.commit_group;" ::: "memory");
    };

    // prologue: stages 0..STAGES-2
#pragma unroll
    for (int s = 0; s < STAGES - 1; s++) load_stage(s, s);

    for (int i = 0; i < NCH; i++) {
        asm volatile("cp.async.wait_group %0;" :: "n"(STAGES - 2) : "memory");
        __syncthreads();

        if (i + STAGES - 1 < NCH)
            load_stage(i + STAGES - 1, (i + STAGES - 1) % STAGES);

        const int slot = i % STAGES;
        const float* a = As + slot * TILE_F + (warpM * 64) * LDP;
        const float* b = Bs + slot * TILE_F + (warpN * 32) * LDP;

#pragma unroll
        for (int ks = 0; ks < 4; ks++) {
            const int k0 = ks * 8;
            uint32_t af[4][4];
#pragma unroll
            for (int mi = 0; mi < 4; mi++) {
                const float* ar = a + (mi * 16 + gid) * LDP + k0 + tig;
                af[mi][0] = __float_as_uint(ar[0]);
                af[mi][1] = __float_as_uint(ar[8 * LDP]);
                af[mi][2] = __float_as_uint(ar[4]);
                af[mi][3] = __float_as_uint(ar[8 * LDP + 4]);
            }
            uint32_t bf[4][2];
#pragma unroll
            for (int ni = 0; ni < 4; ni++) {
                const float* br = b + (ni * 8 + gid) * LDP + k0 + tig;
                bf[ni][0] = __float_as_uint(br[0]);
                bf[ni][1] = __float_as_uint(br[4]);
            }
#pragma unroll
            for (int mi = 0; mi < 4; mi++)
#pragma unroll
                for (int ni = 0; ni < 4; ni++)
                    mma_tf32_16888(acc[mi][ni], af[mi], bf[ni]);
        }
    }

    // ---- epilogue: bias + store (float2 per fragment row) ----
#pragma unroll
    for (int mi = 0; mi < 4; mi++) {
        const int row = mBase + warpM * 64 + mi * 16 + gid;
#pragma unroll
        for (int ni = 0; ni < 4; ni++) {
            const int col = oBase + warpN * 32 + ni * 8 + tig * 2;
            float2 b2 = *(const float2*)(bias + col);
            float2 o0, o1;
            o0.x = acc[mi][ni][0] + b2.x;
            o0.y = acc[mi][ni][1] + b2.y;
            o1.x = acc[mi][ni][2] + b2.x;
            o1.y = acc[mi][ni][3] + b2.y;
            *(float2*)(out + (size_t)row * DOUT + col) = o0;
            *(float2*)(out + (size_t)(row + 8) * DOUT + col) = o1;
        }
    }
}

// ---------------------------------------------------------------------------
// Inputs: x, lora_mapping, weight, bias, lora_a, lora_b, scaling
// ---------------------------------------------------------------------------
extern "C" void kernel_launch(void* const* d_in, const int* in_sizes, int n_in,
                              void* d_out, int out_size)
{
    const float* x       = (const float*)d_in[0];
    const int*   mapping = (const int*)  d_in[1];
    const float* weight  = (const float*)d_in[2];
    const float* bias    = (const float*)d_in[3];
    const float* lora_a  = (const float*)d_in[4];
    const float* lora_b  = (const float*)d_in[5];
    const float* scaling = (const float*)d_in[6];
    float*       out     = (float*)d_out;

    cudaFuncSetAttribute(gemm_mma_kernel,
                         cudaFuncAttributeMaxDynamicSharedMemorySize, SMEM_BYTES);

    prep_x_kernel<<<NTOK / 8, 256>>>(x, mapping, lora_a, scaling);
    prep_w_kernel<<<DOUT / 8, 256>>>(weight, lora_b);

    dim3 grid(DOUT / BN, NTOK / BM);
    gemm_mma_kernel<<<grid, 256, SMEM_BYTES>>>(bias, out);
}

// round 4
// speedup vs baseline: 5.2078x; 1.2845x over previous
#include <cuda_runtime.h>
#include <cuda_fp16.h>
#include <cstdint>

// ---------------------------------------------------------------------------
// Problem constants
// ---------------------------------------------------------------------------
#define NTOK   16384      // B*S
#define DIN    2048
#define DOUT   2048
#define RANK   16
#define NADAPT 8
#define KEXT   (NADAPT*RANK)    // 128 extra K columns holding LoRA
#define KTOT   (DIN + KEXT)     // 2176

// Main GEMM tiling (fp16 operands, fp32 accum)
#define BM 128
#define BN 128
#define BK2 64                  // fp16 elements per chunk = 128 bytes/row
#define NCH (KTOT / BK2)        // 34 K-chunks
#define STAGES 3
#define LDPH 72                 // padded smem row in halves (144 B, conflict-free)
#define TILE_H (BM * LDPH)      // halves per tile per stage
#define SMEM_BYTES (STAGES * TILE_H * 2 * sizeof(__half))   // 110592

// fp16 K-extended operand buffers
__device__ __half g_xh[(size_t)NTOK * KTOT];   // [NTOK, 2176]
__device__ __half g_wh[(size_t)DOUT * KTOT];   // [DOUT, 2176]
__device__ __half g_ah[(size_t)NADAPT * RANK * DIN];  // [128, 2048] all adapters' A

// ---------------------------------------------------------------------------
// Helpers
// ---------------------------------------------------------------------------
__device__ __forceinline__ uint32_t smem_u32(const void* p) {
    uint32_t a;
    asm("{ .reg .u64 t; cvta.to.shared.u64 t, %1; cvt.u32.u64 %0, t; }"
        : "=r"(a) : "l"(p));
    return a;
}

__device__ __forceinline__ void cp_async16(uint32_t dst, const void* src) {
    asm volatile("cp.async.cg.shared.global [%0], [%1], 16;"
                 :: "r"(dst), "l"(src) : "memory");
}

__device__ __forceinline__ void mma_f16_16816(
    float* c, const uint32_t* a, const uint32_t* b)
{
    asm volatile(
        "mma.sync.aligned.m16n8k16.row.col.f32.f16.f16.f32 "
        "{%0,%1,%2,%3}, {%4,%5,%6,%7}, {%8,%9}, {%0,%1,%2,%3};"
        : "+f"(c[0]), "+f"(c[1]), "+f"(c[2]), "+f"(c[3])
        : "r"(a[0]), "r"(a[1]), "r"(a[2]), "r"(a[3]),
          "r"(b[0]), "r"(b[1]));
}

__device__ __forceinline__ uint32_t pack_h2(float x, float y) {
    __half2 h = __float22half2_rn(make_float2(x, y));
    return *reinterpret_cast<uint32_t*>(&h);
}

// ---------------------------------------------------------------------------
// prep_a: convert lora_a [8*16*2048] fp32 -> g_ah fp16
// ---------------------------------------------------------------------------
__global__ void __launch_bounds__(256) prep_a_kernel(const float* __restrict__ lora_a)
{
    int i = blockIdx.x * blockDim.x + threadIdx.x;   // one float4 each
    const float4 v = *(const float4*)(lora_a + (size_t)i * 4);
    uint32_t h01 = pack_h2(v.x, v.y);
    uint32_t h23 = pack_h2(v.z, v.w);
    uint2 o = make_uint2(h01, h23);
    *(uint2*)(g_ah + (size_t)i * 4) = o;
}

// ---------------------------------------------------------------------------
// prep_w: W fp32 -> g_wh fp16 main cols; lora_b packed into ext cols.
// One warp per output row.
// ---------------------------------------------------------------------------
__global__ void __launch_bounds__(256) prep_w_kernel(
    const float* __restrict__ W,
    const float* __restrict__ lora_b)
{
    int o = (blockIdx.x * blockDim.x + threadIdx.x) >> 5;
    int lane = threadIdx.x & 31;
    if (o >= DOUT) return;

    const float* wr = W + (size_t)o * DIN;
    __half* orow = g_wh + (size_t)o * KTOT;

    for (int d0 = lane * 4; d0 < DIN; d0 += 128) {
        float4 wv = *(const float4*)(wr + d0);
        uint2 ov = make_uint2(pack_h2(wv.x, wv.y), pack_h2(wv.z, wv.w));
        *(uint2*)(orow + d0) = ov;
    }

    int e0 = lane * 4;          // 0..124, covers all 128 ext columns
    int a = e0 >> 4;
    int r0 = e0 & 15;
    float4 lb = *(const float4*)(lora_b + ((size_t)a * DOUT + o) * RANK + r0);
    uint2 ov = make_uint2(pack_h2(lb.x, lb.y), pack_h2(lb.z, lb.w));
    *(uint2*)(orow + DIN + e0) = ov;
}

// ---------------------------------------------------------------------------
// prep_xu: per 128-token block:
//   - convert x tile to fp16 -> g_xh[:, 0:2048]
//   - U = x_fp16 @ A_all_fp16^T via mma (128 x 128, K=2048)
//   - ext cols: g_xh[n, 2048+c] = (c>>4 == aid-1) ? scale*U[n,c] : 0
// ---------------------------------------------------------------------------
#define PLDP 72   // padded row in halves for prep smem

__global__ void __launch_bounds__(256, 1) prep_xu_kernel(
    const float* __restrict__ x,
    const int*   __restrict__ mapping,
    const float* __restrict__ scaling)
{
    __shared__ __half xs[128 * PLDP];
    __shared__ __half as_[128 * PLDP];

    const int tid  = threadIdx.x;
    const int wid  = tid >> 5;
    const int lane = tid & 31;
    const int gid  = lane >> 2;
    const int tig  = lane & 3;
    const int warpM = wid >> 2;     // 0..1 (64 token-rows)
    const int warpN = wid & 3;      // 0..3 (32 ar-cols)
    const int tBase = blockIdx.x * 128;

    float acc[4][4][4];
#pragma unroll
    for (int mi = 0; mi < 4; mi++)
#pragma unroll
        for (int ni = 0; ni < 4; ni++)
#pragma unroll
            for (int q = 0; q < 4; q++) acc[mi][ni][q] = 0.0f;

    for (int ch = 0; ch < DIN / BK2; ch++) {
        const int k0g = ch * BK2;
        // stage x: 128 rows x 16 float4 segs = 2048 -> 8 per thread
#pragma unroll
        for (int t = 0; t < 8; t++) {
            int idx = tid + t * 256;
            int row = idx >> 4, seg = idx & 15;
            float4 v = *(const float4*)(x + (size_t)(tBase + row) * DIN + k0g + seg * 4);
            uint2 h = make_uint2(pack_h2(v.x, v.y), pack_h2(v.z, v.w));
            *(uint2*)(xs + row * PLDP + seg * 4) = h;
            *(uint2*)(g_xh + (size_t)(tBase + row) * KTOT + k0g + seg * 4) = h;
        }
        // stage A: 128 rows x 8 uint4 segs = 1024 -> 4 per thread (already fp16)
#pragma unroll
        for (int t = 0; t < 4; t++) {
            int idx = tid + t * 256;
            int row = idx >> 3, seg = idx & 7;
            uint4 v = *(const uint4*)(g_ah + (size_t)row * DIN + k0g + seg * 8);
            *(uint4*)(as_ + row * PLDP + seg * 8) = v;
        }
        __syncthreads();

        const __half* a = xs + (warpM * 64) * PLDP;
        const __half* b = as_ + (warpN * 32) * PLDP;
#pragma unroll
        for (int ks = 0; ks < 4; ks++) {
            const int k0 = ks * 16;
            uint32_t af[4][4];
#pragma unroll
            for (int mi = 0; mi < 4; mi++) {
                const __half* ar = a + (mi * 16 + gid) * PLDP + k0 + 2 * tig;
                af[mi][0] = *(const uint32_t*)(ar);
                af[mi][1] = *(const uint32_t*)(ar + 8 * PLDP);
                af[mi][2] = *(const uint32_t*)(ar + 8);
                af[mi][3] = *(const uint32_t*)(ar + 8 * PLDP + 8);
            }
            uint32_t bf[4][2];
#pragma unroll
            for (int ni = 0; ni < 4; ni++) {
                const __half* br = b + (ni * 8 + gid) * PLDP + k0 + 2 * tig;
                bf[ni][0] = *(const uint32_t*)(br);
                bf[ni][1] = *(const uint32_t*)(br + 8);
            }
#pragma unroll
            for (int mi = 0; mi < 4; mi++)
#pragma unroll
                for (int ni = 0; ni < 4; ni++)
                    mma_f16_16816(acc[mi][ni], af[mi], bf[ni]);
        }
        __syncthreads();
    }

    // epilogue: select adapter slice, scale, write ext cols as fp16
#pragma unroll
    for (int mi = 0; mi < 4; mi++) {
        const int r0 = warpM * 64 + mi * 16 + gid;
        const int r1 = r0 + 8;
        const int aid0 = mapping[tBase + r0];
        const int aid1 = mapping[tBase + r1];
        const float s0 = (aid0 > 0) ? scaling[aid0 - 1] : 0.0f;
        const float s1 = (aid1 > 0) ? scaling[aid1 - 1] : 0.0f;
#pragma unroll
        for (int ni = 0; ni < 4; ni++) {
            const int col = warpN * 32 + ni * 8 + tig * 2;
            const bool sel0 = (aid0 > 0) && ((col >> 4) == aid0 - 1);
            const bool sel1 = (aid1 > 0) && ((col >> 4) == aid1 - 1);
            uint32_t v0 = sel0 ? pack_h2(acc[mi][ni][0] * s0, acc[mi][ni][1] * s0) : 0u;
            uint32_t v1 = sel1 ? pack_h2(acc[mi][ni][2] * s1, acc[mi][ni][3] * s1) : 0u;
            *(uint32_t*)(g_xh + (size_t)(tBase + r0) * KTOT + DIN + col) = v0;
            *(uint32_t*)(g_xh + (size_t)(tBase + r1) * KTOT + DIN + col) = v1;
        }
    }
}

// ---------------------------------------------------------------------------
// Main GEMM (fp16 mma): out[n,o] = g_xh[n,:] . g_wh[o,:] + bias[o]
// CTA 128x128xK, 8 warps (2x4), warp tile 64x32, m16n8k16, 3-stage cp.async.
// ---------------------------------------------------------------------------
__global__ void __launch_bounds__(256, 1) gemm_h_kernel(
    const float* __restrict__ bias, float* __restrict__ out)
{
    extern __shared__ __half smem[];
    const int tid  = threadIdx.x;
    const int wid  = tid >> 5;
    const int lane = tid & 31;
    const int gid  = lane >> 2;
    const int tig  = lane & 3;
    const int warpM = wid >> 2;
    const int warpN = wid & 3;
    const int mBase = blockIdx.y * BM;
    const int oBase = blockIdx.x * BN;

    __half* As = smem;                      // [STAGES][BM][LDPH]
    __half* Bs = smem + STAGES * TILE_H;    // [STAGES][BN][LDPH]

    float acc[4][4][4];
#pragma unroll
    for (int mi = 0; mi < 4; mi++)
#pragma unroll
        for (int ni = 0; ni < 4; ni++)
#pragma unroll
            for (int q = 0; q < 4; q++) acc[mi][ni][q] = 0.0f;

    // staging: 128 rows x 8 x 16B segs = 1024 per tile -> 4 per thread
    const int lrow = tid >> 3;
    const int lseg = tid & 7;

    auto load_stage = [&](int chunk, int slot) {
        __half* a = As + slot * TILE_H;
        __half* b = Bs + slot * TILE_H;
        const size_t koff = (size_t)chunk * BK2 + lseg * 8;
#pragma unroll
        for (int t = 0; t < 4; t++) {
            int row = lrow + t * 32;
            cp_async16(smem_u32(a + row * LDPH + lseg * 8),
                       g_xh + (size_t)(mBase + row) * KTOT + koff);
            cp_async16(smem_u32(b + row * LDPH + lseg * 8),
                       g_wh + (size_t)(oBase + row) * KTOT + koff);
        }
        asm volatile("cp.async.commit_group;" ::: "memory");
    };

#pragma unroll
    for (int s = 0; s < STAGES - 1; s++) load_stage(s, s);

    for (int i = 0; i < NCH; i++) {
        asm volatile("cp.async.wait_group %0;" :: "n"(STAGES - 2) : "memory");
        __syncthreads();

        if (i + STAGES - 1 < NCH)
            load_stage(i + STAGES - 1, (i + STAGES - 1) % STAGES);

        const int slot = i % STAGES;
        const __half* a = As + slot * TILE_H + (warpM * 64) * LDPH;
        const __half* b = Bs + slot * TILE_H + (warpN * 32) * LDPH;

#pragma unroll
        for (int ks = 0; ks < 4; ks++) {
            const int k0 = ks * 16;
            uint32_t af[4][4];
#pragma unroll
            for (int mi = 0; mi < 4; mi++) {
                const __half* ar = a + (mi * 16 + gid) * LDPH + k0 + 2 * tig;
                af[mi][0] = *(const uint32_t*)(ar);
                af[mi][1] = *(const uint32_t*)(ar + 8 * LDPH);
                af[mi][2] = *(const uint32_t*)(ar + 8);
                af[mi][3] = *(const uint32_t*)(ar + 8 * LDPH + 8);
            }
            uint32_t bf[4][2];
#pragma unroll
            for (int ni = 0; ni < 4; ni++) {
                const __half* br = b + (ni * 8 + gid) * LDPH + k0 + 2 * tig;
                bf[ni][0] = *(const uint32_t*)(br);
                bf[ni][1] = *(const uint32_t*)(br + 8);
            }
#pragma unroll
            for (int mi = 0; mi < 4; mi++)
#pragma unroll
                for (int ni = 0; ni < 4; ni++)
                    mma_f16_16816(acc[mi][ni], af[mi], bf[ni]);
        }
    }

    // epilogue: bias + store
#pragma unroll
    for (int mi = 0; mi < 4; mi++) {
        const int row = mBase + warpM * 64 + mi * 16 + gid;
#pragma unroll
        for (int ni = 0; ni < 4; ni++) {
            const int col = oBase + warpN * 32 + ni * 8 + tig * 2;
            float2 b2 = *(const float2*)(bias + col);
            float2 o0, o1;
            o0.x = acc[mi][ni][0] + b2.x;
            o0.y = acc[mi][ni][1] + b2.y;
            o1.x = acc[mi][ni][2] + b2.x;
            o1.y = acc[mi][ni][3] + b2.y;
            *(float2*)(out + (size_t)row * DOUT + col) = o0;
            *(float2*)(out + (size_t)(row + 8) * DOUT + col) = o1;
        }
    }
}

// ---------------------------------------------------------------------------
// Inputs: x, lora_mapping, weight, bias, lora_a, lora_b, scaling
// ---------------------------------------------------------------------------
extern "C" void kernel_launch(void* const* d_in, const int* in_sizes, int n_in,
                              void* d_out, int out_size)
{
    const float* x       = (const float*)d_in[0];
    const int*   mapping = (const int*)  d_in[1];
    const float* weight  = (const float*)d_in[2];
    const float* bias    = (const float*)d_in[3];
    const float* lora_a  = (const float*)d_in[4];
    const float* lora_b  = (const float*)d_in[5];
    const float* scaling = (const float*)d_in[6];
    float*       out     = (float*)d_out;

    cudaFuncSetAttribute(gemm_h_kernel,
                         cudaFuncAttributeMaxDynamicSharedMemorySize, SMEM_BYTES);

    prep_a_kernel<<<(NADAPT * RANK * DIN / 4) / 256, 256>>>(lora_a);
    prep_w_kernel<<<DOUT / 8, 256>>>(weight, lora_b);
    prep_xu_kernel<<<NTOK / 128, 256>>>(x, mapping, scaling);

    dim3 grid(DOUT / BN, NTOK / BM);
    gemm_h_kernel<<<grid, 256, SMEM_BYTES>>>(bias, out);
}

// round 5
// speedup vs baseline: 10.4204x; 2.0009x over previous
#include <cuda_runtime.h>
#include <cuda_fp16.h>
#include <cstdint>

// ---------------------------------------------------------------------------
// Problem constants
// ---------------------------------------------------------------------------
#define NTOK   16384      // B*S
#define DIN    2048
#define DOUT   2048
#define RANK   16
#define NADAPT 8
#define KEXT   (NADAPT*RANK)    // 128 extra K columns holding LoRA
#define KTOT   (DIN + KEXT)     // 2176

// Main GEMM tiling (fp16 operands, fp32 accum)
#define BM 256
#define BN 128
#define BK2 64                  // fp16 per chunk = 128 bytes/row
#define NCH (KTOT / BK2)        // 34 K-chunks
#define STAGES 3
#define A_ST_BYTES (BM * 128)   // 32768
#define B_ST_BYTES (BN * 128)   // 16384
#define ST_BYTES   (A_ST_BYTES + B_ST_BYTES)       // 49152
#define SMEM_BYTES (STAGES * ST_BYTES)             // 147456

// fp16 K-extended operand buffers
__device__ __half g_xh[(size_t)NTOK * KTOT];   // [NTOK, 2176]
__device__ __half g_wh[(size_t)DOUT * KTOT];   // [DOUT, 2176]
__device__ __half g_ah[(size_t)NADAPT * RANK * DIN];  // [128, 2048]

// ---------------------------------------------------------------------------
// Helpers
// ---------------------------------------------------------------------------
__device__ __forceinline__ uint32_t smem_u32(const void* p) {
    uint32_t a;
    asm("{ .reg .u64 t; cvta.to.shared.u64 t, %1; cvt.u32.u64 %0, t; }"
        : "=r"(a) : "l"(p));
    return a;
}

__device__ __forceinline__ void cp_async16(uint32_t dst, const void* src) {
    asm volatile("cp.async.cg.shared.global [%0], [%1], 16;"
                 :: "r"(dst), "l"(src) : "memory");
}

__device__ __forceinline__ void ldsm_x4(uint32_t* r, uint32_t addr) {
    asm volatile("ldmatrix.sync.aligned.m8n8.x4.shared.b16 {%0,%1,%2,%3}, [%4];"
                 : "=r"(r[0]), "=r"(r[1]), "=r"(r[2]), "=r"(r[3]) : "r"(addr));
}

__device__ __forceinline__ void mma_f16_16816(
    float* c, const uint32_t* a, const uint32_t* b)
{
    asm volatile(
        "mma.sync.aligned.m16n8k16.row.col.f32.f16.f16.f32 "
        "{%0,%1,%2,%3}, {%4,%5,%6,%7}, {%8,%9}, {%0,%1,%2,%3};"
        : "+f"(c[0]), "+f"(c[1]), "+f"(c[2]), "+f"(c[3])
        : "r"(a[0]), "r"(a[1]), "r"(a[2]), "r"(a[3]),
          "r"(b[0]), "r"(b[1]));
}

__device__ __forceinline__ uint32_t pack_h2(float x, float y) {
    __half2 h = __float22half2_rn(make_float2(x, y));
    return *reinterpret_cast<uint32_t*>(&h);
}

// ---------------------------------------------------------------------------
// prep_a: lora_a fp32 -> g_ah fp16
// ---------------------------------------------------------------------------
__global__ void __launch_bounds__(256) prep_a_kernel(const float* __restrict__ lora_a)
{
    int i = blockIdx.x * blockDim.x + threadIdx.x;
    const float4 v = *(const float4*)(lora_a + (size_t)i * 4);
    uint2 o = make_uint2(pack_h2(v.x, v.y), pack_h2(v.z, v.w));
    *(uint2*)(g_ah + (size_t)i * 4) = o;
}

// ---------------------------------------------------------------------------
// prep_w: W fp32 -> g_wh main cols; lora_b packed into ext cols. 1 warp/row.
// ---------------------------------------------------------------------------
__global__ void __launch_bounds__(256) prep_w_kernel(
    const float* __restrict__ W,
    const float* __restrict__ lora_b)
{
    int o = (blockIdx.x * blockDim.x + threadIdx.x) >> 5;
    int lane = threadIdx.x & 31;
    if (o >= DOUT) return;

    const float* wr = W + (size_t)o * DIN;
    __half* orow = g_wh + (size_t)o * KTOT;

    for (int d0 = lane * 4; d0 < DIN; d0 += 128) {
        float4 wv = *(const float4*)(wr + d0);
        uint2 ov = make_uint2(pack_h2(wv.x, wv.y), pack_h2(wv.z, wv.w));
        *(uint2*)(orow + d0) = ov;
    }

    int e0 = lane * 4;
    int a = e0 >> 4;
    int r0 = e0 & 15;
    float4 lb = *(const float4*)(lora_b + ((size_t)a * DOUT + o) * RANK + r0);
    uint2 ov = make_uint2(pack_h2(lb.x, lb.y), pack_h2(lb.z, lb.w));
    *(uint2*)(orow + DIN + e0) = ov;
}

// ---------------------------------------------------------------------------
// prep_xu: per 128-token block: x->fp16 into g_xh; U = x @ A_all^T via mma;
// ext cols = select(aid)*scale*U.
// ---------------------------------------------------------------------------
#define PLDP 72

__global__ void __launch_bounds__(256, 1) prep_xu_kernel(
    const float* __restrict__ x,
    const int*   __restrict__ mapping,
    const float* __restrict__ scaling)
{
    __shared__ __half xs[128 * PLDP];
    __shared__ __half as_[128 * PLDP];

    const int tid  = threadIdx.x;
    const int wid  = tid >> 5;
    const int lane = tid & 31;
    const int gid  = lane >> 2;
    const int tig  = lane & 3;
    const int warpM = wid >> 2;
    const int warpN = wid & 3;
    const int tBase = blockIdx.x * 128;

    float acc[4][4][4];
#pragma unroll
    for (int mi = 0; mi < 4; mi++)
#pragma unroll
        for (int ni = 0; ni < 4; ni++)
#pragma unroll
            for (int q = 0; q < 4; q++) acc[mi][ni][q] = 0.0f;

    for (int ch = 0; ch < DIN / 64; ch++) {
        const int k0g = ch * 64;
#pragma unroll
        for (int t = 0; t < 8; t++) {
            int idx = tid + t * 256;
            int row = idx >> 4, seg = idx & 15;
            float4 v = *(const float4*)(x + (size_t)(tBase + row) * DIN + k0g + seg * 4);
            uint2 h = make_uint2(pack_h2(v.x, v.y), pack_h2(v.z, v.w));
            *(uint2*)(xs + row * PLDP + seg * 4) = h;
            *(uint2*)(g_xh + (size_t)(tBase + row) * KTOT + k0g + seg * 4) = h;
        }
#pragma unroll
        for (int t = 0; t < 4; t++) {
            int idx = tid + t * 256;
            int row = idx >> 3, seg = idx & 7;
            uint4 v = *(const uint4*)(g_ah + (size_t)row * DIN + k0g + seg * 8);
            *(uint4*)(as_ + row * PLDP + seg * 8) = v;
        }
        __syncthreads();

        const __half* a = xs + (warpM * 64) * PLDP;
        const __half* b = as_ + (warpN * 32) * PLDP;
#pragma unroll
        for (int ks = 0; ks < 4; ks++) {
            const int k0 = ks * 16;
            uint32_t af[4][4];
#pragma unroll
            for (int mi = 0; mi < 4; mi++) {
                const __half* ar = a + (mi * 16 + gid) * PLDP + k0 + 2 * tig;
                af[mi][0] = *(const uint32_t*)(ar);
                af[mi][1] = *(const uint32_t*)(ar + 8 * PLDP);
                af[mi][2] = *(const uint32_t*)(ar + 8);
                af[mi][3] = *(const uint32_t*)(ar + 8 * PLDP + 8);
            }
            uint32_t bf[4][2];
#pragma unroll
            for (int ni = 0; ni < 4; ni++) {
                const __half* br = b + (ni * 8 + gid) * PLDP + k0 + 2 * tig;
                bf[ni][0] = *(const uint32_t*)(br);
                bf[ni][1] = *(const uint32_t*)(br + 8);
            }
#pragma unroll
            for (int mi = 0; mi < 4; mi++)
#pragma unroll
                for (int ni = 0; ni < 4; ni++)
                    mma_f16_16816(acc[mi][ni], af[mi], bf[ni]);
        }
        __syncthreads();
    }

#pragma unroll
    for (int mi = 0; mi < 4; mi++) {
        const int r0 = warpM * 64 + mi * 16 + gid;
        const int r1 = r0 + 8;
        const int aid0 = mapping[tBase + r0];
        const int aid1 = mapping[tBase + r1];
        const float s0 = (aid0 > 0) ? scaling[aid0 - 1] : 0.0f;
        const float s1 = (aid1 > 0) ? scaling[aid1 - 1] : 0.0f;
#pragma unroll
        for (int ni = 0; ni < 4; ni++) {
            const int col = warpN * 32 + ni * 8 + tig * 2;
            const bool sel0 = (aid0 > 0) && ((col >> 4) == aid0 - 1);
            const bool sel1 = (aid1 > 0) && ((col >> 4) == aid1 - 1);
            uint32_t v0 = sel0 ? pack_h2(acc[mi][ni][0] * s0, acc[mi][ni][1] * s0) : 0u;
            uint32_t v1 = sel1 ? pack_h2(acc[mi][ni][2] * s1, acc[mi][ni][3] * s1) : 0u;
            *(uint32_t*)(g_xh + (size_t)(tBase + r0) * KTOT + DIN + col) = v0;
            *(uint32_t*)(g_xh + (size_t)(tBase + r1) * KTOT + DIN + col) = v1;
        }
    }
}

// ---------------------------------------------------------------------------
// Main GEMM: CTA 256x128, 8 warps (4x2), warp tile 64x64, ldmatrix + m16n8k16.
// Swizzled smem (seg ^ row&7), 3-stage cp.async pipeline.
// ---------------------------------------------------------------------------
__global__ void __launch_bounds__(256, 1) gemm_h_kernel(
    const float* __restrict__ bias, float* __restrict__ out)
{
    extern __shared__ char smem[];
    const uint32_t sb = smem_u32(smem);
    const int tid  = threadIdx.x;
    const int wid  = tid >> 5;
    const int lane = tid & 31;
    const int gid  = lane >> 2;
    const int tig  = lane & 3;
    const int warpM = wid & 3;      // 0..3 -> 64 rows each
    const int warpN = wid >> 2;     // 0..1 -> 64 cols each
    const int mBase = blockIdx.y * BM;
    const int oBase = blockIdx.x * BN;
    const uint32_t lane7 = lane & 7;

    float acc[4][8][4];
#pragma unroll
    for (int mi = 0; mi < 4; mi++)
#pragma unroll
        for (int n = 0; n < 8; n++)
#pragma unroll
            for (int q = 0; q < 4; q++) acc[mi][n][q] = 0.0f;

    // staging indices: 16B chunk (row, seg)
    const int lrow = tid >> 3;      // 0..31
    const int lseg = tid & 7;       // 0..7
    const uint32_t st_off = (uint32_t)(lseg ^ (lrow & 7)) * 16;

    auto load_stage = [&](int chunk, int slot) {
        const uint32_t abase = sb + slot * ST_BYTES;
        const uint32_t bbase = abase + A_ST_BYTES;
        const size_t koff = (size_t)chunk * BK2 + lseg * 8;
#pragma unroll
        for (int t = 0; t < 8; t++) {           // A: 256 rows
            int row = lrow + t * 32;
            cp_async16(abase + row * 128 + st_off,
                       g_xh + (size_t)(mBase + row) * KTOT + koff);
        }
#pragma unroll
        for (int t = 0; t < 4; t++) {           // B: 128 rows
            int row = lrow + t * 32;
            cp_async16(bbase + row * 128 + st_off,
                       g_wh + (size_t)(oBase + row) * KTOT + koff);
        }
        asm volatile("cp.async.commit_group;" ::: "memory");
    };

#pragma unroll
    for (int s = 0; s < STAGES - 1; s++) load_stage(s, s);

    // ldmatrix lane addressing (constant per thread)
    const int ra = (lane & 7) + ((lane >> 3) & 1) * 8;   // A row-in-16-tile
    const int ka = lane >> 4;                            // A k-seg select 0/1
    const int rb = (lane & 7) + ((lane >> 4) & 1) * 8;   // B row-in-16-tile
    const int kb = (lane >> 3) & 1;                      // B k-seg select 0/1

    for (int i = 0; i < NCH; i++) {
        asm volatile("cp.async.wait_group %0;" :: "n"(STAGES - 2) : "memory");
        __syncthreads();

        if (i + STAGES - 1 < NCH)
            load_stage(i + STAGES - 1, (i + STAGES - 1) % STAGES);

        const int slot = i % STAGES;
        const uint32_t aw = sb + slot * ST_BYTES + (warpM * 64) * 128;
        const uint32_t bw = sb + slot * ST_BYTES + A_ST_BYTES + (warpN * 64) * 128;

#pragma unroll
        for (int ks = 0; ks < 4; ks++) {
            uint32_t af[4][4];
#pragma unroll
            for (int mi = 0; mi < 4; mi++) {
                uint32_t addr = aw + (mi * 16 + ra) * 128
                              + (((uint32_t)(ks * 2 + ka) ^ lane7) * 16);
                ldsm_x4(af[mi], addr);
            }
            uint32_t bf[8][2];
#pragma unroll
            for (int nj = 0; nj < 4; nj++) {
                uint32_t t[4];
                uint32_t addr = bw + (nj * 16 + rb) * 128
                              + (((uint32_t)(ks * 2 + kb) ^ lane7) * 16);
                ldsm_x4(t, addr);
                bf[2 * nj][0] = t[0]; bf[2 * nj][1] = t[1];
                bf[2 * nj + 1][0] = t[2]; bf[2 * nj + 1][1] = t[3];
            }
#pragma unroll
            for (int mi = 0; mi < 4; mi++)
#pragma unroll
                for (int n = 0; n < 8; n++)
                    mma_f16_16816(acc[mi][n], af[mi], bf[n]);
        }
    }

    // epilogue: bias + store
#pragma unroll
    for (int mi = 0; mi < 4; mi++) {
        const int row = mBase + warpM * 64 + mi * 16 + gid;
#pragma unroll
        for (int n = 0; n < 8; n++) {
            const int col = oBase + warpN * 64 + n * 8 + tig * 2;
            float2 b2 = *(const float2*)(bias + col);
            float2 o0, o1;
            o0.x = acc[mi][n][0] + b2.x;
            o0.y = acc[mi][n][1] + b2.y;
            o1.x = acc[mi][n][2] + b2.x;
            o1.y = acc[mi][n][3] + b2.y;
            *(float2*)(out + (size_t)row * DOUT + col) = o0;
            *(float2*)(out + (size_t)(row + 8) * DOUT + col) = o1;
        }
    }
}

// ---------------------------------------------------------------------------
// Inputs: x, lora_mapping, weight, bias, lora_a, lora_b, scaling
// ---------------------------------------------------------------------------
extern "C" void kernel_launch(void* const* d_in, const int* in_sizes, int n_in,
                              void* d_out, int out_size)
{
    const float* x       = (const float*)d_in[0];
    const int*   mapping = (const int*)  d_in[1];
    const float* weight  = (const float*)d_in[2];
    const float* bias    = (const float*)d_in[3];
    const float* lora_a  = (const float*)d_in[4];
    const float* lora_b  = (const float*)d_in[5];
    const float* scaling = (const float*)d_in[6];
    float*       out     = (float*)d_out;

    cudaFuncSetAttribute(gemm_h_kernel,
                         cudaFuncAttributeMaxDynamicSharedMemorySize, SMEM_BYTES);

    prep_a_kernel<<<(NADAPT * RANK * DIN / 4) / 256, 256>>>(lora_a);
    prep_w_kernel<<<DOUT / 8, 256>>>(weight, lora_b);
    prep_xu_kernel<<<NTOK / 128, 256>>>(x, mapping, scaling);

    dim3 grid(DOUT / BN, NTOK / BM);
    gemm_h_kernel<<<grid, 256, SMEM_BYTES>>>(bias, out);
}

// round 6
// speedup vs baseline: 10.8843x; 1.0445x over previous
#include <cuda_runtime.h>
#include <cuda_fp16.h>
#include <cstdint>

// ---------------------------------------------------------------------------
// Problem constants
// ---------------------------------------------------------------------------
#define NTOK   16384      // B*S
#define DIN    2048
#define DOUT   2048
#define RANK   16
#define NADAPT 8
#define KEXT   (NADAPT*RANK)    // 128 extra K columns holding LoRA
#define KTOT   (DIN + KEXT)     // 2176

// Main GEMM tiling (fp16 operands, fp32 accum)
#define BM 256
#define BN 128
#define BK2 64                  // fp16 per chunk = 128 bytes/row
#define NCH (KTOT / BK2)        // 34 K-chunks
#define STAGES 4
#define A_ST_BYTES (BM * 128)   // 32768
#define B_ST_BYTES (BN * 128)   // 16384
#define ST_BYTES   (A_ST_BYTES + B_ST_BYTES)       // 49152
#define SMEM_BYTES (STAGES * ST_BYTES)             // 196608

// prep_xu: 2-stage double buffer, 128x128B per tile
#define P_ST_BYTES 16384
#define P_SMEM_BYTES (2 * 2 * P_ST_BYTES)          // 65536

// fp16 K-extended operand buffers
__device__ __half g_xh[(size_t)NTOK * KTOT];   // [NTOK, 2176]
__device__ __half g_wh[(size_t)DOUT * KTOT];   // [DOUT, 2176]
__device__ __half g_ah[(size_t)NADAPT * RANK * DIN];  // [128, 2048]

// ---------------------------------------------------------------------------
// Helpers
// ---------------------------------------------------------------------------
__device__ __forceinline__ uint32_t smem_u32(const void* p) {
    uint32_t a;
    asm("{ .reg .u64 t; cvta.to.shared.u64 t, %1; cvt.u32.u64 %0, t; }"
        : "=r"(a) : "l"(p));
    return a;
}

__device__ __forceinline__ void cp_async16(uint32_t dst, const void* src) {
    asm volatile("cp.async.cg.shared.global [%0], [%1], 16;"
                 :: "r"(dst), "l"(src) : "memory");
}

__device__ __forceinline__ void ldsm_x4(uint32_t* r, uint32_t addr) {
    asm volatile("ldmatrix.sync.aligned.m8n8.x4.shared.b16 {%0,%1,%2,%3}, [%4];"
                 : "=r"(r[0]), "=r"(r[1]), "=r"(r[2]), "=r"(r[3]) : "r"(addr));
}

__device__ __forceinline__ void mma_f16_16816(
    float* c, const uint32_t* a, const uint32_t* b)
{
    asm volatile(
        "mma.sync.aligned.m16n8k16.row.col.f32.f16.f16.f32 "
        "{%0,%1,%2,%3}, {%4,%5,%6,%7}, {%8,%9}, {%0,%1,%2,%3};"
        : "+f"(c[0]), "+f"(c[1]), "+f"(c[2]), "+f"(c[3])
        : "r"(a[0]), "r"(a[1]), "r"(a[2]), "r"(a[3]),
          "r"(b[0]), "r"(b[1]));
}

__device__ __forceinline__ uint32_t pack_h2(float x, float y) {
    __half2 h = __float22half2_rn(make_float2(x, y));
    return *reinterpret_cast<uint32_t*>(&h);
}

// ---------------------------------------------------------------------------
// prep_a: lora_a fp32 -> g_ah fp16
// ---------------------------------------------------------------------------
__global__ void __launch_bounds__(256) prep_a_kernel(const float* __restrict__ lora_a)
{
    int i = blockIdx.x * blockDim.x + threadIdx.x;
    const float4 v = *(const float4*)(lora_a + (size_t)i * 4);
    uint2 o = make_uint2(pack_h2(v.x, v.y), pack_h2(v.z, v.w));
    *(uint2*)(g_ah + (size_t)i * 4) = o;
}

// ---------------------------------------------------------------------------
// prep_w: W fp32 -> g_wh main cols; lora_b packed into ext cols. 1 warp/row.
// ---------------------------------------------------------------------------
__global__ void __launch_bounds__(256) prep_w_kernel(
    const float* __restrict__ W,
    const float* __restrict__ lora_b)
{
    int o = (blockIdx.x * blockDim.x + threadIdx.x) >> 5;
    int lane = threadIdx.x & 31;
    if (o >= DOUT) return;

    const float* wr = W + (size_t)o * DIN;
    __half* orow = g_wh + (size_t)o * KTOT;

    for (int d0 = lane * 4; d0 < DIN; d0 += 128) {
        float4 wv = *(const float4*)(wr + d0);
        uint2 ov = make_uint2(pack_h2(wv.x, wv.y), pack_h2(wv.z, wv.w));
        *(uint2*)(orow + d0) = ov;
    }

    int e0 = lane * 4;
    int a = e0 >> 4;
    int r0 = e0 & 15;
    float4 lb = *(const float4*)(lora_b + ((size_t)a * DOUT + o) * RANK + r0);
    uint2 ov = make_uint2(pack_h2(lb.x, lb.y), pack_h2(lb.z, lb.w));
    *(uint2*)(orow + DIN + e0) = ov;
}

// ---------------------------------------------------------------------------
// prep_xu: per 128-token block: x->fp16 into g_xh; U = x @ A_all^T via
// ldmatrix+mma; ext cols = select(aid)*scale*U. 2-stage smem double buffer.
// ---------------------------------------------------------------------------
__global__ void __launch_bounds__(256, 1) prep_xu_kernel(
    const float* __restrict__ x,
    const int*   __restrict__ mapping,
    const float* __restrict__ scaling)
{
    extern __shared__ char psmem[];
    const uint32_t sb = smem_u32(psmem);
    const int tid  = threadIdx.x;
    const int wid  = tid >> 5;
    const int lane = tid & 31;
    const int gid  = lane >> 2;
    const int tig  = lane & 3;
    const int warpM = wid >> 2;     // 0..1 -> 64 token-rows
    const int warpN = wid & 3;      // 0..3 -> 32 U-cols
    const int tBase = blockIdx.x * 128;
    const uint32_t lane7 = lane & 7;

    const int lrow = tid >> 3;      // 0..31
    const int lseg = tid & 7;       // 0..7
    const uint32_t sw_off = (uint32_t)(lseg ^ (lrow & 7)) * 16;

    float acc[4][4][4];
#pragma unroll
    for (int mi = 0; mi < 4; mi++)
#pragma unroll
        for (int ni = 0; ni < 4; ni++)
#pragma unroll
            for (int q = 0; q < 4; q++) acc[mi][ni][q] = 0.0f;

    auto load_stage = [&](int ch, int s) {
        const uint32_t xbase = sb + s * (2 * P_ST_BYTES);
        const uint32_t abase = xbase + P_ST_BYTES;
        const int k0g = ch * 64;
#pragma unroll
        for (int t = 0; t < 4; t++) {
            int row = lrow + t * 32;
            // x: fp32 -> fp16, write smem (swizzled) + g_xh (linear)
            const float* xp = x + (size_t)(tBase + row) * DIN + k0g + lseg * 8;
            float4 v0 = *(const float4*)(xp);
            float4 v1 = *(const float4*)(xp + 4);
            uint4 h = make_uint4(pack_h2(v0.x, v0.y), pack_h2(v0.z, v0.w),
                                 pack_h2(v1.x, v1.y), pack_h2(v1.z, v1.w));
            *(uint4*)((char*)psmem + (xbase - sb) + row * 128 + sw_off) = h;
            *(uint4*)(g_xh + (size_t)(tBase + row) * KTOT + k0g + lseg * 8) = h;
            // A: already fp16
            uint4 av = *(const uint4*)(g_ah + (size_t)row * DIN + k0g + lseg * 8);
            *(uint4*)((char*)psmem + (abase - sb) + row * 128 + sw_off) = av;
        }
    };

    // ldmatrix lane addressing (validated pattern from main GEMM)
    const int ra = (lane & 7) + ((lane >> 3) & 1) * 8;
    const int ka = lane >> 4;
    const int rb = (lane & 7) + ((lane >> 4) & 1) * 8;
    const int kb = (lane >> 3) & 1;

    load_stage(0, 0);
    __syncthreads();

    for (int ch = 0; ch < DIN / 64; ch++) {
        const int s = ch & 1;
        if (ch + 1 < DIN / 64) load_stage(ch + 1, s ^ 1);

        const uint32_t aw = sb + s * (2 * P_ST_BYTES) + (warpM * 64) * 128;
        const uint32_t bw = sb + s * (2 * P_ST_BYTES) + P_ST_BYTES + (warpN * 32) * 128;

#pragma unroll
        for (int ks = 0; ks < 4; ks++) {
            uint32_t af[4][4];
#pragma unroll
            for (int mi = 0; mi < 4; mi++) {
                uint32_t addr = aw + (mi * 16 + ra) * 128
                              + (((uint32_t)(ks * 2 + ka) ^ lane7) * 16);
                ldsm_x4(af[mi], addr);
            }
            uint32_t bf[4][2];
#pragma unroll
            for (int nj = 0; nj < 2; nj++) {
                uint32_t t[4];
                uint32_t addr = bw + (nj * 16 + rb) * 128
                              + (((uint32_t)(ks * 2 + kb) ^ lane7) * 16);
                ldsm_x4(t, addr);
                bf[2 * nj][0] = t[0]; bf[2 * nj][1] = t[1];
                bf[2 * nj + 1][0] = t[2]; bf[2 * nj + 1][1] = t[3];
            }
#pragma unroll
            for (int mi = 0; mi < 4; mi++)
#pragma unroll
                for (int ni = 0; ni < 4; ni++)
                    mma_f16_16816(acc[mi][ni], af[mi], bf[ni]);
        }
        __syncthreads();
    }

    // epilogue: select adapter slice, scale, write ext cols
#pragma unroll
    for (int mi = 0; mi < 4; mi++) {
        const int r0 = warpM * 64 + mi * 16 + gid;
        const int r1 = r0 + 8;
        const int aid0 = mapping[tBase + r0];
        const int aid1 = mapping[tBase + r1];
        const float s0 = (aid0 > 0) ? scaling[aid0 - 1] : 0.0f;
        const float s1 = (aid1 > 0) ? scaling[aid1 - 1] : 0.0f;
#pragma unroll
        for (int ni = 0; ni < 4; ni++) {
            const int col = warpN * 32 + ni * 8 + tig * 2;
            const bool sel0 = (aid0 > 0) && ((col >> 4) == aid0 - 1);
            const bool sel1 = (aid1 > 0) && ((col >> 4) == aid1 - 1);
            uint32_t v0 = sel0 ? pack_h2(acc[mi][ni][0] * s0, acc[mi][ni][1] * s0) : 0u;
            uint32_t v1 = sel1 ? pack_h2(acc[mi][ni][2] * s1, acc[mi][ni][3] * s1) : 0u;
            *(uint32_t*)(g_xh + (size_t)(tBase + r0) * KTOT + DIN + col) = v0;
            *(uint32_t*)(g_xh + (size_t)(tBase + r1) * KTOT + DIN + col) = v1;
        }
    }
}

// ---------------------------------------------------------------------------
// Main GEMM: CTA 256x128, 16 warps (4Mx4N), warp tile 64x32.
// ldmatrix + m16n8k16, swizzled smem, 4-stage cp.async pipeline.
// ---------------------------------------------------------------------------
__global__ void __launch_bounds__(512, 1) gemm_h_kernel(
    const float* __restrict__ bias, float* __restrict__ out)
{
    extern __shared__ char smem[];
    const uint32_t sb = smem_u32(smem);
    const int tid  = threadIdx.x;
    const int wid  = tid >> 5;
    const int lane = tid & 31;
    const int gid  = lane >> 2;
    const int tig  = lane & 3;
    const int warpM = wid & 3;      // 0..3 -> 64 rows each
    const int warpN = wid >> 2;     // 0..3 -> 32 cols each
    const int mBase = blockIdx.y * BM;
    const int oBase = blockIdx.x * BN;
    const uint32_t lane7 = lane & 7;

    float acc[4][4][4];
#pragma unroll
    for (int mi = 0; mi < 4; mi++)
#pragma unroll
        for (int n = 0; n < 4; n++)
#pragma unroll
            for (int q = 0; q < 4; q++) acc[mi][n][q] = 0.0f;

    // staging: 512 threads, 16B chunk (row, seg)
    const int lrow = tid >> 3;      // 0..63
    const int lseg = tid & 7;       // 0..7
    const uint32_t st_off = (uint32_t)(lseg ^ (lrow & 7)) * 16;

    auto load_stage = [&](int chunk, int slot) {
        const uint32_t abase = sb + slot * ST_BYTES;
        const uint32_t bbase = abase + A_ST_BYTES;
        const size_t koff = (size_t)chunk * BK2 + lseg * 8;
#pragma unroll
        for (int t = 0; t < 4; t++) {           // A: 256 rows
            int row = lrow + t * 64;
            cp_async16(abase + row * 128 + st_off,
                       g_xh + (size_t)(mBase + row) * KTOT + koff);
        }
#pragma unroll
        for (int t = 0; t < 2; t++) {           // B: 128 rows
            int row = lrow + t * 64;
            cp_async16(bbase + row * 128 + st_off,
                       g_wh + (size_t)(oBase + row) * KTOT + koff);
        }
        asm volatile("cp.async.commit_group;" ::: "memory");
    };

#pragma unroll
    for (int s = 0; s < STAGES - 1; s++) load_stage(s, s);

    // ldmatrix lane addressing (constant per thread)
    const int ra = (lane & 7) + ((lane >> 3) & 1) * 8;
    const int ka = lane >> 4;
    const int rb = (lane & 7) + ((lane >> 4) & 1) * 8;
    const int kb = (lane >> 3) & 1;

    for (int i = 0; i < NCH; i++) {
        asm volatile("cp.async.wait_group %0;" :: "n"(STAGES - 2) : "memory");
        __syncthreads();

        if (i + STAGES - 1 < NCH)
            load_stage(i + STAGES - 1, (i + STAGES - 1) % STAGES);

        const int slot = i % STAGES;
        const uint32_t aw = sb + slot * ST_BYTES + (warpM * 64) * 128;
        const uint32_t bw = sb + slot * ST_BYTES + A_ST_BYTES + (warpN * 32) * 128;

#pragma unroll
        for (int ks = 0; ks < 4; ks++) {
            uint32_t af[4][4];
#pragma unroll
            for (int mi = 0; mi < 4; mi++) {
                uint32_t addr = aw + (mi * 16 + ra) * 128
                              + (((uint32_t)(ks * 2 + ka) ^ lane7) * 16);
                ldsm_x4(af[mi], addr);
            }
            uint32_t bf[4][2];
#pragma unroll
            for (int nj = 0; nj < 2; nj++) {
                uint32_t t[4];
                uint32_t addr = bw + (nj * 16 + rb) * 128
                              + (((uint32_t)(ks * 2 + kb) ^ lane7) * 16);
                ldsm_x4(t, addr);
                bf[2 * nj][0] = t[0]; bf[2 * nj][1] = t[1];
                bf[2 * nj + 1][0] = t[2]; bf[2 * nj + 1][1] = t[3];
            }
#pragma unroll
            for (int mi = 0; mi < 4; mi++)
#pragma unroll
                for (int n = 0; n < 4; n++)
                    mma_f16_16816(acc[mi][n], af[mi], bf[n]);
        }
    }

    // epilogue: bias + store
#pragma unroll
    for (int mi = 0; mi < 4; mi++) {
        const int row = mBase + warpM * 64 + mi * 16 + gid;
#pragma unroll
        for (int n = 0; n < 4; n++) {
            const int col = oBase + warpN * 32 + n * 8 + tig * 2;
            float2 b2 = *(const float2*)(bias + col);
            float2 o0, o1;
            o0.x = acc[mi][n][0] + b2.x;
            o0.y = acc[mi][n][1] + b2.y;
            o1.x = acc[mi][n][2] + b2.x;
            o1.y = acc[mi][n][3] + b2.y;
            *(float2*)(out + (size_t)row * DOUT + col) = o0;
            *(float2*)(out + (size_t)(row + 8) * DOUT + col) = o1;
        }
    }
}

// ---------------------------------------------------------------------------
// Inputs: x, lora_mapping, weight, bias, lora_a, lora_b, scaling
// ---------------------------------------------------------------------------
extern "C" void kernel_launch(void* const* d_in, const int* in_sizes, int n_in,
                              void* d_out, int out_size)
{
    const float* x       = (const float*)d_in[0];
    const int*   mapping = (const int*)  d_in[1];
    const float* weight  = (const float*)d_in[2];
    const float* bias    = (const float*)d_in[3];
    const float* lora_a  = (const float*)d_in[4];
    const float* lora_b  = (const float*)d_in[5];
    const float* scaling = (const float*)d_in[6];
    float*       out     = (float*)d_out;

    cudaFuncSetAttribute(gemm_h_kernel,
                         cudaFuncAttributeMaxDynamicSharedMemorySize, SMEM_BYTES);
    cudaFuncSetAttribute(prep_xu_kernel,
                         cudaFuncAttributeMaxDynamicSharedMemorySize, P_SMEM_BYTES);

    prep_a_kernel<<<(NADAPT * RANK * DIN / 4) / 256, 256>>>(lora_a);
    prep_w_kernel<<<DOUT / 8, 256>>>(weight, lora_b);
    prep_xu_kernel<<<NTOK / 128, 256, P_SMEM_BYTES>>>(x, mapping, scaling);

    dim3 grid(DOUT / BN, NTOK / BM);
    gemm_h_kernel<<<grid, 512, SMEM_BYTES>>>(bias, out);
}